// round 1
// baseline (speedup 1.0000x reference)
#include <cuda_runtime.h>
#include <cstdint>

#define N_NODES_MAX 100000
#define N_EDGES_MAX 1600000

// ---------------- device scratch (no allocations allowed) ----------------
__device__ float g_h[(size_t)N_NODES_MAX * 128];   // GEMM output (pre-aggregation)
__device__ float g_y[(size_t)N_NODES_MAX * 128];   // layer output (next layer input)
__device__ float g_dinv[N_NODES_MAX];
__device__ int   g_count[N_NODES_MAX];
__device__ int   g_fill[N_NODES_MAX];
__device__ int   g_rowptr[N_NODES_MAX + 1];
__device__ int   g_esrc[N_EDGES_MAX];
__device__ float g_enorm[N_EDGES_MAX];
__device__ int   g_bsums[256];
__device__ int   g_is32;   // 1 if edge_index is int32, 0 if int64

// ---------------- helpers ----------------
__device__ __forceinline__ int edge_val(const void* ei, int is32, long long idx) {
    if (is32) return ((const int*)ei)[idx];
    return (int)((const long long*)ei)[idx];
}

// ---------------- preprocessing kernels ----------------
__global__ void k_detect(const void* ei, int E, long long N) {
    if (blockIdx.x == 0 && threadIdx.x == 0) {
        const long long* p = (const long long*)ei;
        int is32 = 0;
        for (int i = 0; i < 64 && i < E; i++) {
            long long v = p[i];
            if (v < 0 || v >= N) { is32 = 1; break; }
        }
        g_is32 = is32;
    }
}

__global__ void k_zero(int n) {
    int i = blockIdx.x * blockDim.x + threadIdx.x;
    if (i < n) { g_count[i] = 0; g_fill[i] = 0; }
}

__global__ void k_hist(const void* __restrict__ ei, int E) {
    int e = blockIdx.x * blockDim.x + threadIdx.x;
    if (e >= E) return;
    int is32 = g_is32;
    int d = edge_val(ei, is32, (long long)E + e);
    atomicAdd(&g_count[d], 1);
}

__global__ void k_dinv(int n) {
    int i = blockIdx.x * blockDim.x + threadIdx.x;
    if (i < n) g_dinv[i] = rsqrtf((float)g_count[i] + 1.0f);
}

__global__ void k_scan1(int n) {
    __shared__ int s[1024];
    int t = threadIdx.x;
    int i = blockIdx.x * 1024 + t;
    int v = (i < n) ? g_count[i] : 0;
    s[t] = v;
    __syncthreads();
    #pragma unroll
    for (int off = 1; off < 1024; off <<= 1) {
        int x = (t >= off) ? s[t - off] : 0;
        __syncthreads();
        s[t] += x;
        __syncthreads();
    }
    if (i < n) g_rowptr[i] = s[t] - v;      // block-local exclusive
    if (t == 1023) g_bsums[blockIdx.x] = s[1023];
}

__global__ void k_scan2(int nb, int n) {
    if (threadIdx.x == 0 && blockIdx.x == 0) {
        int acc = 0;
        for (int b = 0; b < nb; b++) { int t = g_bsums[b]; g_bsums[b] = acc; acc += t; }
        g_rowptr[n] = acc;
    }
}

__global__ void k_scan3(int n) {
    int i = blockIdx.x * blockDim.x + threadIdx.x;
    if (i < n) g_rowptr[i] += g_bsums[i >> 10];
}

__global__ void k_scatter(const void* __restrict__ ei, int E) {
    int e = blockIdx.x * blockDim.x + threadIdx.x;
    if (e >= E) return;
    int is32 = g_is32;
    int s = edge_val(ei, is32, e);
    int d = edge_val(ei, is32, (long long)E + e);
    int pos = g_rowptr[d] + atomicAdd(&g_fill[d], 1);
    g_esrc[pos]  = s;
    g_enorm[pos] = g_dinv[s] * g_dinv[d];
}

// ---------------- GEMM: C[M,SC(cols 0..NT)] = A[M,KT] @ W[KT,NT] ----------------
// BM=128, BK=16, 256 threads, thread tile 8 x TN.
template<int KT, int NT, int BN, int TN, int SC>
__global__ __launch_bounds__(256) void k_gemm(const float* __restrict__ A,
                                              const float* __restrict__ W,
                                              float* __restrict__ C, int M) {
    constexpr int BM = 128, BK = 16;
    __shared__ float As[BK][BM];
    __shared__ float Ws[BK][BN];
    const int tid = threadIdx.x;
    const int tx = tid % 16;   // 16 col-groups (BN/TN == 16)
    const int ty = tid / 16;   // 16 row-groups of 8 rows
    const int row0 = blockIdx.x * BM;

    float acc[8][TN];
    #pragma unroll
    for (int i = 0; i < 8; i++)
        #pragma unroll
        for (int j = 0; j < TN; j++) acc[i][j] = 0.f;

    for (int k0 = 0; k0 < KT; k0 += BK) {
        // A tile: 128x16 floats = 512 float4, 2 per thread, store transposed
        #pragma unroll
        for (int l = 0; l < 2; l++) {
            int idx = tid + l * 256;
            int r = idx >> 2, c4 = idx & 3;
            int grow = row0 + r;
            float4 v = make_float4(0.f, 0.f, 0.f, 0.f);
            if (grow < M) v = *(const float4*)(A + (size_t)grow * KT + k0 + c4 * 4);
            As[c4 * 4 + 0][r] = v.x;
            As[c4 * 4 + 1][r] = v.y;
            As[c4 * 4 + 2][r] = v.z;
            As[c4 * 4 + 3][r] = v.w;
        }
        // W tile: BK x BN, zero-padded beyond NT
        #pragma unroll
        for (int l = 0; l < (BK * BN) / 256; l++) {
            int idx = tid + l * 256;
            int r = idx / BN, c = idx % BN;
            Ws[r][c] = (c < NT) ? W[(size_t)(k0 + r) * NT + c] : 0.f;
        }
        __syncthreads();
        #pragma unroll
        for (int k = 0; k < BK; k++) {
            float ra[8], rb[TN];
            #pragma unroll
            for (int i = 0; i < 8; i++) ra[i] = As[k][ty * 8 + i];
            #pragma unroll
            for (int j = 0; j < TN; j++) rb[j] = Ws[k][tx * TN + j];
            #pragma unroll
            for (int i = 0; i < 8; i++)
                #pragma unroll
                for (int j = 0; j < TN; j++) acc[i][j] += ra[i] * rb[j];
        }
        __syncthreads();
    }
    #pragma unroll
    for (int i = 0; i < 8; i++) {
        int grow = row0 + ty * 8 + i;
        if (grow < M) {
            #pragma unroll
            for (int j = 0; j < TN; j += 4) {
                float4 v = make_float4(acc[i][j], acc[i][j + 1], acc[i][j + 2], acc[i][j + 3]);
                *(float4*)(C + (size_t)grow * SC + tx * TN + j) = v;
            }
        }
    }
}

// ---------------- aggregation: warp per node, CSR, no atomics ----------------
// out[i][f] = act( sum_edges norm*h[src][f] + dinv[i]^2 * h[i][f] + b[f] )
template<int NF, int C, int SH, int SO, bool RELU>
__global__ __launch_bounds__(256) void k_agg(const float* __restrict__ h,
                                             const float* __restrict__ b,
                                             float* __restrict__ out, int n) {
    int warp = (blockIdx.x * blockDim.x + threadIdx.x) >> 5;
    int lane = threadIdx.x & 31;
    if (warp >= n) return;
    const int i = warp;
    int e = g_rowptr[i];
    const int e1 = g_rowptr[i + 1];

    float acc[NF];
    #pragma unroll
    for (int j = 0; j < NF; j++) acc[j] = 0.f;

    // 2-way edge unroll for MLP (L2-latency hiding)
    for (; e + 1 < e1; e += 2) {
        int s0 = g_esrc[e], s1 = g_esrc[e + 1];
        float n0 = g_enorm[e], n1 = g_enorm[e + 1];
        const float* h0 = h + (size_t)s0 * SH;
        const float* h1 = h + (size_t)s1 * SH;
        #pragma unroll
        for (int j = 0; j < NF; j++) {
            int f = lane + j * 32;
            if (f < C) {
                acc[j] += n0 * __ldg(h0 + f);
                acc[j] += n1 * __ldg(h1 + f);
            }
        }
    }
    if (e < e1) {
        int s0 = g_esrc[e];
        float n0 = g_enorm[e];
        const float* h0 = h + (size_t)s0 * SH;
        #pragma unroll
        for (int j = 0; j < NF; j++) {
            int f = lane + j * 32;
            if (f < C) acc[j] += n0 * __ldg(h0 + f);
        }
    }

    float di = g_dinv[i];
    float sl = di * di;
    const float* hi = h + (size_t)i * SH;
    #pragma unroll
    for (int j = 0; j < NF; j++) {
        int f = lane + j * 32;
        if (f < C) {
            float v = acc[j] + sl * __ldg(hi + f) + __ldg(b + f);
            if (RELU) v = fmaxf(v, 0.f);
            out[(size_t)i * SO + f] = v;
        }
    }
}

// ---------------- launch ----------------
extern "C" void kernel_launch(void* const* d_in, const int* in_sizes, int n_in,
                              void* d_out, int out_size) {
    const float* x  = (const float*)d_in[0];
    const void*  ei = d_in[1];
    const float* W1 = (const float*)d_in[2];  const float* b1 = (const float*)d_in[3];
    const float* W2 = (const float*)d_in[4];  const float* b2 = (const float*)d_in[5];
    const float* W3 = (const float*)d_in[6];  const float* b3 = (const float*)d_in[7];
    const float* W4 = (const float*)d_in[8];  const float* b4 = (const float*)d_in[9];
    const float* W5 = (const float*)d_in[10]; const float* b5 = (const float*)d_in[11];

    const int N = in_sizes[0] / 384;
    const int E = in_sizes[1] / 2;

    float *h, *y;
    cudaGetSymbolAddress((void**)&h, g_h);
    cudaGetSymbolAddress((void**)&y, g_y);

    const int T = 256;
    const int gN = (N + T - 1) / T;
    const int gE = (E + T - 1) / T;
    const int nb = (N + 1023) / 1024;
    const int gm = (N + 127) / 128;
    const int ga = (N + 7) / 8;   // warp per node, 8 warps/block

    // preprocessing: degrees, dinv, CSR by dst
    k_detect<<<1, 32>>>(ei, E, (long long)N);
    k_zero<<<gN, T>>>(N);
    k_hist<<<gE, T>>>(ei, E);
    k_dinv<<<gN, T>>>(N);
    k_scan1<<<nb, 1024>>>(N);
    k_scan2<<<1, 32>>>(nb, N);
    k_scan3<<<gN, T>>>(N);
    k_scatter<<<gE, T>>>(ei, E);

    // layer 1: 384 -> 128, relu
    k_gemm<384, 128, 128, 8, 128><<<gm, T>>>(x, W1, h, N);
    k_agg<4, 128, 128, 128, true><<<ga, T>>>(h, b1, y, N);
    // layer 2
    k_gemm<128, 128, 128, 8, 128><<<gm, T>>>(y, W2, h, N);
    k_agg<4, 128, 128, 128, true><<<ga, T>>>(h, b2, y, N);
    // layer 3
    k_gemm<128, 128, 128, 8, 128><<<gm, T>>>(y, W3, h, N);
    k_agg<4, 128, 128, 128, true><<<ga, T>>>(h, b3, y, N);
    // layer 4
    k_gemm<128, 128, 128, 8, 128><<<gm, T>>>(y, W4, h, N);
    k_agg<4, 128, 128, 128, true><<<ga, T>>>(h, b4, y, N);
    // layer 5: 128 -> 50, no relu, writes d_out (stride 50)
    k_gemm<128, 50, 64, 4, 64><<<gm, T>>>(y, W5, h, N);
    k_agg<2, 50, 64, 50, false><<<ga, T>>>(h, b5, (float*)d_out, N);
}

// round 2
// speedup vs baseline: 1.0865x; 1.0865x over previous
#include <cuda_runtime.h>
#include <cstdint>

#define N_NODES_MAX 100000
#define N_EDGES_MAX 1600000

// ---------------- device scratch (no allocations allowed) ----------------
__device__ float g_h[(size_t)N_NODES_MAX * 128];   // GEMM output (pre-aggregation)
__device__ float g_y[(size_t)N_NODES_MAX * 128];   // layer output (next layer input)
__device__ float g_dinv[N_NODES_MAX];
__device__ int   g_count[N_NODES_MAX];
__device__ int   g_fill[N_NODES_MAX];
__device__ int   g_rowptr[N_NODES_MAX + 1];
__device__ int   g_esrc[N_EDGES_MAX];
__device__ float g_enorm[N_EDGES_MAX];
__device__ int   g_bsums[256];
__device__ int   g_is32;   // 1 if edge_index is int32, 0 if int64

// ---------------- f32x2 packed-math helpers (Blackwell double-rate fp32) ----
__device__ __forceinline__ unsigned long long f2_dup(float a) {
    unsigned long long r;
    asm("mov.b64 %0, {%1, %1};" : "=l"(r) : "f"(a));
    return r;
}
__device__ __forceinline__ unsigned long long f2_fma(unsigned long long a,
                                                     unsigned long long b,
                                                     unsigned long long c) {
    unsigned long long d;
    asm("fma.rn.f32x2 %0, %1, %2, %3;" : "=l"(d) : "l"(a), "l"(b), "l"(c));
    return d;
}
__device__ __forceinline__ void f2_unpack(unsigned long long v, float& a, float& b) {
    asm("mov.b64 {%0, %1}, %2;" : "=f"(a), "=f"(b) : "l"(v));
}

// ---------------- misc helpers ----------------
__device__ __forceinline__ int edge_val(const void* ei, int is32, long long idx) {
    if (is32) return ((const int*)ei)[idx];
    return (int)((const long long*)ei)[idx];
}

// ---------------- preprocessing kernels ----------------
__global__ void k_detect(const void* ei, int E, long long N) {
    if (blockIdx.x == 0 && threadIdx.x == 0) {
        const long long* p = (const long long*)ei;
        int is32 = 0;
        for (int i = 0; i < 64 && i < E; i++) {
            long long v = p[i];
            if (v < 0 || v >= N) { is32 = 1; break; }
        }
        g_is32 = is32;
    }
}

__global__ void k_zero(int n) {
    int i = blockIdx.x * blockDim.x + threadIdx.x;
    if (i < n) { g_count[i] = 0; g_fill[i] = 0; }
}

__global__ void k_hist(const void* __restrict__ ei, int E) {
    int e = blockIdx.x * blockDim.x + threadIdx.x;
    if (e >= E) return;
    int is32 = g_is32;
    int d = edge_val(ei, is32, (long long)E + e);
    atomicAdd(&g_count[d], 1);
}

__global__ void k_dinv(int n) {
    int i = blockIdx.x * blockDim.x + threadIdx.x;
    if (i < n) g_dinv[i] = rsqrtf((float)g_count[i] + 1.0f);
}

__global__ void k_scan1(int n) {
    __shared__ int s[1024];
    int t = threadIdx.x;
    int i = blockIdx.x * 1024 + t;
    int v = (i < n) ? g_count[i] : 0;
    s[t] = v;
    __syncthreads();
    #pragma unroll
    for (int off = 1; off < 1024; off <<= 1) {
        int x = (t >= off) ? s[t - off] : 0;
        __syncthreads();
        s[t] += x;
        __syncthreads();
    }
    if (i < n) g_rowptr[i] = s[t] - v;      // block-local exclusive
    if (t == 1023) g_bsums[blockIdx.x] = s[1023];
}

__global__ void k_scan2(int nb, int n) {
    if (threadIdx.x == 0 && blockIdx.x == 0) {
        int acc = 0;
        for (int b = 0; b < nb; b++) { int t = g_bsums[b]; g_bsums[b] = acc; acc += t; }
        g_rowptr[n] = acc;
    }
}

__global__ void k_scan3(int n) {
    int i = blockIdx.x * blockDim.x + threadIdx.x;
    if (i < n) g_rowptr[i] += g_bsums[i >> 10];
}

__global__ void k_scatter(const void* __restrict__ ei, int E) {
    int e = blockIdx.x * blockDim.x + threadIdx.x;
    if (e >= E) return;
    int is32 = g_is32;
    int s = edge_val(ei, is32, e);
    int d = edge_val(ei, is32, (long long)E + e);
    int pos = g_rowptr[d] + atomicAdd(&g_fill[d], 1);
    g_esrc[pos]  = s;
    g_enorm[pos] = g_dinv[s] * g_dinv[d];
}

// ---------------- GEMM: C[M,SC(cols 0..NT)] = A[M,KT] @ W[KT,NT] ----------------
// BM=128, BK=16, 256 threads, thread tile 8 x TN, packed f32x2 FMAs,
// double-buffered shared memory with register prefetch.
template<int KT, int NT, int BN, int TN, int SC>
__global__ __launch_bounds__(256) void k_gemm(const float* __restrict__ A,
                                              const float* __restrict__ W,
                                              float* __restrict__ C, int M) {
    constexpr int BM = 128, BK = 16;
    constexpr int TNH = TN / 2;
    constexpr int WL = (BK * BN) / 256;
    __shared__ float As[2][BK][BM];
    __shared__ float Ws[2][BK][BN];
    const int tid = threadIdx.x;
    const int tx = tid % 16;   // 16 col-groups (BN/TN == 16)
    const int ty = tid / 16;   // 16 row-groups of 8 rows
    const int row0 = blockIdx.x * BM;

    // A-load indexing: idx = tid + l*256; r = idx>>2 in [0,128), c4 = idx&3
    const int ar = tid >> 2;
    const int ac4 = tid & 3;

    unsigned long long acc[8][TNH];
    #pragma unroll
    for (int i = 0; i < 8; i++)
        #pragma unroll
        for (int j = 0; j < TNH; j++) acc[i][j] = 0ULL;

    float4 pa[2];
    float  pw[WL];

    // prefetch first tile into registers
    {
        const int k0 = 0;
        #pragma unroll
        for (int l = 0; l < 2; l++) {
            int grow = row0 + ar + l * 64;
            pa[l] = make_float4(0.f, 0.f, 0.f, 0.f);
            if (grow < M) pa[l] = *(const float4*)(A + (size_t)grow * KT + k0 + ac4 * 4);
        }
        #pragma unroll
        for (int l = 0; l < WL; l++) {
            int idx = tid + l * 256;
            int r = idx / BN, c = idx % BN;
            pw[l] = (c < NT) ? W[(size_t)(k0 + r) * NT + c] : 0.f;
        }
    }
    // store first tile to stage 0
    #pragma unroll
    for (int l = 0; l < 2; l++) {
        int r = ar + l * 64;
        As[0][ac4 * 4 + 0][r] = pa[l].x;
        As[0][ac4 * 4 + 1][r] = pa[l].y;
        As[0][ac4 * 4 + 2][r] = pa[l].z;
        As[0][ac4 * 4 + 3][r] = pa[l].w;
    }
    #pragma unroll
    for (int l = 0; l < WL; l++) {
        int idx = tid + l * 256;
        Ws[0][idx / BN][idx % BN] = pw[l];
    }
    __syncthreads();

    int cur = 0;
    for (int k0 = 0; k0 < KT; k0 += BK) {
        const bool more = (k0 + BK < KT);
        if (more) {
            const int kn = k0 + BK;
            #pragma unroll
            for (int l = 0; l < 2; l++) {
                int grow = row0 + ar + l * 64;
                pa[l] = make_float4(0.f, 0.f, 0.f, 0.f);
                if (grow < M) pa[l] = *(const float4*)(A + (size_t)grow * KT + kn + ac4 * 4);
            }
            #pragma unroll
            for (int l = 0; l < WL; l++) {
                int idx = tid + l * 256;
                int r = idx / BN, c = idx % BN;
                pw[l] = (c < NT) ? W[(size_t)(kn + r) * NT + c] : 0.f;
            }
        }

        #pragma unroll
        for (int k = 0; k < BK; k++) {
            float4 a0 = *(const float4*)&As[cur][k][ty * 8];
            float4 a1 = *(const float4*)&As[cur][k][ty * 8 + 4];
            unsigned long long rb[TNH];
            #pragma unroll
            for (int j = 0; j < TNH; j += 2) {
                ulonglong2 t = *(const ulonglong2*)&Ws[cur][k][tx * TN + j * 2];
                rb[j] = t.x; rb[j + 1] = t.y;
            }
            float ra[8] = {a0.x, a0.y, a0.z, a0.w, a1.x, a1.y, a1.z, a1.w};
            #pragma unroll
            for (int i = 0; i < 8; i++) {
                unsigned long long a2 = f2_dup(ra[i]);
                #pragma unroll
                for (int j = 0; j < TNH; j++) acc[i][j] = f2_fma(a2, rb[j], acc[i][j]);
            }
        }

        if (more) {
            int nxt = cur ^ 1;
            #pragma unroll
            for (int l = 0; l < 2; l++) {
                int r = ar + l * 64;
                As[nxt][ac4 * 4 + 0][r] = pa[l].x;
                As[nxt][ac4 * 4 + 1][r] = pa[l].y;
                As[nxt][ac4 * 4 + 2][r] = pa[l].z;
                As[nxt][ac4 * 4 + 3][r] = pa[l].w;
            }
            #pragma unroll
            for (int l = 0; l < WL; l++) {
                int idx = tid + l * 256;
                Ws[nxt][idx / BN][idx % BN] = pw[l];
            }
            __syncthreads();
            cur = nxt;
        }
    }

    #pragma unroll
    for (int i = 0; i < 8; i++) {
        int grow = row0 + ty * 8 + i;
        if (grow < M) {
            float o[TN];
            #pragma unroll
            for (int j = 0; j < TNH; j++) f2_unpack(acc[i][j], o[2 * j], o[2 * j + 1]);
            #pragma unroll
            for (int j = 0; j < TN; j += 4) {
                float4 v = make_float4(o[j], o[j + 1], o[j + 2], o[j + 3]);
                *(float4*)(C + (size_t)grow * SC + tx * TN + j) = v;
            }
        }
    }
}

// ---------------- aggregation (C=128): warp per node, float4 lanes ----------
template<bool RELU>
__global__ __launch_bounds__(256) void k_agg128(const float* __restrict__ h,
                                                const float* __restrict__ b,
                                                float* __restrict__ out, int n) {
    int warp = (blockIdx.x * blockDim.x + threadIdx.x) >> 5;
    int lane = threadIdx.x & 31;
    if (warp >= n) return;
    const float4* __restrict__ h4 = (const float4*)h;
    int e = g_rowptr[warp];
    const int e1 = g_rowptr[warp + 1];

    float4 acc = make_float4(0.f, 0.f, 0.f, 0.f);

    for (; e + 4 <= e1; e += 4) {
        int s0 = g_esrc[e], s1 = g_esrc[e + 1], s2 = g_esrc[e + 2], s3 = g_esrc[e + 3];
        float n0 = g_enorm[e], n1 = g_enorm[e + 1], n2 = g_enorm[e + 2], n3 = g_enorm[e + 3];
        float4 v0 = __ldg(h4 + s0 * 32 + lane);
        float4 v1 = __ldg(h4 + s1 * 32 + lane);
        float4 v2 = __ldg(h4 + s2 * 32 + lane);
        float4 v3 = __ldg(h4 + s3 * 32 + lane);
        acc.x += n0 * v0.x; acc.y += n0 * v0.y; acc.z += n0 * v0.z; acc.w += n0 * v0.w;
        acc.x += n1 * v1.x; acc.y += n1 * v1.y; acc.z += n1 * v1.z; acc.w += n1 * v1.w;
        acc.x += n2 * v2.x; acc.y += n2 * v2.y; acc.z += n2 * v2.z; acc.w += n2 * v2.w;
        acc.x += n3 * v3.x; acc.y += n3 * v3.y; acc.z += n3 * v3.z; acc.w += n3 * v3.w;
    }
    for (; e < e1; e++) {
        int s0 = g_esrc[e];
        float n0 = g_enorm[e];
        float4 v0 = __ldg(h4 + s0 * 32 + lane);
        acc.x += n0 * v0.x; acc.y += n0 * v0.y; acc.z += n0 * v0.z; acc.w += n0 * v0.w;
    }

    float di = g_dinv[warp];
    float sl = di * di;
    float4 vi = __ldg(h4 + warp * 32 + lane);
    float4 vb = __ldg((const float4*)b + lane);
    acc.x += sl * vi.x + vb.x;
    acc.y += sl * vi.y + vb.y;
    acc.z += sl * vi.z + vb.z;
    acc.w += sl * vi.w + vb.w;
    if (RELU) {
        acc.x = fmaxf(acc.x, 0.f); acc.y = fmaxf(acc.y, 0.f);
        acc.z = fmaxf(acc.z, 0.f); acc.w = fmaxf(acc.w, 0.f);
    }
    ((float4*)out)[warp * 32 + lane] = acc;
}

// ---------------- aggregation (generic C, used for final 50-col layer) ------
template<int NF, int C, int SH, int SO, bool RELU>
__global__ __launch_bounds__(256) void k_agg(const float* __restrict__ h,
                                             const float* __restrict__ b,
                                             float* __restrict__ out, int n) {
    int warp = (blockIdx.x * blockDim.x + threadIdx.x) >> 5;
    int lane = threadIdx.x & 31;
    if (warp >= n) return;
    const int i = warp;
    int e = g_rowptr[i];
    const int e1 = g_rowptr[i + 1];

    float acc[NF];
    #pragma unroll
    for (int j = 0; j < NF; j++) acc[j] = 0.f;

    for (; e + 1 < e1; e += 2) {
        int s0 = g_esrc[e], s1 = g_esrc[e + 1];
        float n0 = g_enorm[e], n1 = g_enorm[e + 1];
        const float* h0 = h + (size_t)s0 * SH;
        const float* h1 = h + (size_t)s1 * SH;
        #pragma unroll
        for (int j = 0; j < NF; j++) {
            int f = lane + j * 32;
            if (f < C) {
                acc[j] += n0 * __ldg(h0 + f);
                acc[j] += n1 * __ldg(h1 + f);
            }
        }
    }
    if (e < e1) {
        int s0 = g_esrc[e];
        float n0 = g_enorm[e];
        const float* h0 = h + (size_t)s0 * SH;
        #pragma unroll
        for (int j = 0; j < NF; j++) {
            int f = lane + j * 32;
            if (f < C) acc[j] += n0 * __ldg(h0 + f);
        }
    }

    float di = g_dinv[i];
    float sl = di * di;
    const float* hi = h + (size_t)i * SH;
    #pragma unroll
    for (int j = 0; j < NF; j++) {
        int f = lane + j * 32;
        if (f < C) {
            float v = acc[j] + sl * __ldg(hi + f) + __ldg(b + f);
            if (RELU) v = fmaxf(v, 0.f);
            out[(size_t)i * SO + f] = v;
        }
    }
}

// ---------------- launch ----------------
extern "C" void kernel_launch(void* const* d_in, const int* in_sizes, int n_in,
                              void* d_out, int out_size) {
    const float* x  = (const float*)d_in[0];
    const void*  ei = d_in[1];
    const float* W1 = (const float*)d_in[2];  const float* b1 = (const float*)d_in[3];
    const float* W2 = (const float*)d_in[4];  const float* b2 = (const float*)d_in[5];
    const float* W3 = (const float*)d_in[6];  const float* b3 = (const float*)d_in[7];
    const float* W4 = (const float*)d_in[8];  const float* b4 = (const float*)d_in[9];
    const float* W5 = (const float*)d_in[10]; const float* b5 = (const float*)d_in[11];

    const int N = in_sizes[0] / 384;
    const int E = in_sizes[1] / 2;

    float *h, *y;
    cudaGetSymbolAddress((void**)&h, g_h);
    cudaGetSymbolAddress((void**)&y, g_y);

    const int T = 256;
    const int gN = (N + T - 1) / T;
    const int gE = (E + T - 1) / T;
    const int nb = (N + 1023) / 1024;
    const int gm = (N + 127) / 128;
    const int ga = (N + 7) / 8;   // warp per node, 8 warps/block

    // preprocessing: degrees, dinv, CSR by dst
    k_detect<<<1, 32>>>(ei, E, (long long)N);
    k_zero<<<gN, T>>>(N);
    k_hist<<<gE, T>>>(ei, E);
    k_dinv<<<gN, T>>>(N);
    k_scan1<<<nb, 1024>>>(N);
    k_scan2<<<1, 32>>>(nb, N);
    k_scan3<<<gN, T>>>(N);
    k_scatter<<<gE, T>>>(ei, E);

    // layer 1: 384 -> 128, relu
    k_gemm<384, 128, 128, 8, 128><<<gm, T>>>(x, W1, h, N);
    k_agg128<true><<<ga, T>>>(h, b1, y, N);
    // layer 2
    k_gemm<128, 128, 128, 8, 128><<<gm, T>>>(y, W2, h, N);
    k_agg128<true><<<ga, T>>>(h, b2, y, N);
    // layer 3
    k_gemm<128, 128, 128, 8, 128><<<gm, T>>>(y, W3, h, N);
    k_agg128<true><<<ga, T>>>(h, b3, y, N);
    // layer 4
    k_gemm<128, 128, 128, 8, 128><<<gm, T>>>(y, W4, h, N);
    k_agg128<true><<<ga, T>>>(h, b4, y, N);
    // layer 5: 128 -> 50, no relu, writes d_out (stride 50)
    k_gemm<128, 50, 64, 4, 64><<<gm, T>>>(y, W5, h, N);
    k_agg<2, 50, 64, 50, false><<<ga, T>>>(h, b5, (float*)d_out, N);
}

// round 3
// speedup vs baseline: 1.5560x; 1.4321x over previous
#include <cuda_runtime.h>
#include <cstdint>

#define N_NODES_MAX 100000
#define N_EDGES_MAX 1600000

// ---------------- device scratch (no allocations allowed) ----------------
__device__ float g_h[(size_t)N_NODES_MAX * 128];   // GEMM output (pre-aggregation)
__device__ float g_y[(size_t)N_NODES_MAX * 128];   // layer output (next layer input)
__device__ float g_dinv[N_NODES_MAX];
__device__ int   g_count[N_NODES_MAX];
__device__ int   g_fill[N_NODES_MAX];
__device__ int   g_rowptr[N_NODES_MAX + 1];
__device__ int   g_esrc[N_EDGES_MAX];
__device__ float g_enorm[N_EDGES_MAX];
__device__ int   g_bsums[256];
__device__ int   g_is32;   // 1 if edge_index is int32, 0 if int64

// ---------------- helpers ----------------
__device__ __forceinline__ int edge_val(const void* ei, int is32, long long idx) {
    if (is32) return ((const int*)ei)[idx];
    return (int)((const long long*)ei)[idx];
}

__device__ __forceinline__ uint32_t to_tf32(float f) {
    uint32_t r;
    asm("cvt.rna.tf32.f32 %0, %1;" : "=r"(r) : "f"(f));
    return r;
}

// ---------------- preprocessing kernels ----------------
__global__ void k_detect(const void* ei, int E, long long N) {
    if (blockIdx.x == 0 && threadIdx.x == 0) {
        const long long* p = (const long long*)ei;
        int is32 = 0;
        for (int i = 0; i < 64 && i < E; i++) {
            long long v = p[i];
            if (v < 0 || v >= N) { is32 = 1; break; }
        }
        g_is32 = is32;
    }
}

__global__ void k_zero(int n) {
    int i = blockIdx.x * blockDim.x + threadIdx.x;
    if (i < n) { g_count[i] = 0; g_fill[i] = 0; }
}

__global__ void k_hist(const void* __restrict__ ei, int E) {
    int e = blockIdx.x * blockDim.x + threadIdx.x;
    if (e >= E) return;
    int is32 = g_is32;
    int d = edge_val(ei, is32, (long long)E + e);
    atomicAdd(&g_count[d], 1);
}

__global__ void k_dinv(int n) {
    int i = blockIdx.x * blockDim.x + threadIdx.x;
    if (i < n) g_dinv[i] = rsqrtf((float)g_count[i] + 1.0f);
}

__global__ void k_scan1(int n) {
    __shared__ int s[1024];
    int t = threadIdx.x;
    int i = blockIdx.x * 1024 + t;
    int v = (i < n) ? g_count[i] : 0;
    s[t] = v;
    __syncthreads();
    #pragma unroll
    for (int off = 1; off < 1024; off <<= 1) {
        int x = (t >= off) ? s[t - off] : 0;
        __syncthreads();
        s[t] += x;
        __syncthreads();
    }
    if (i < n) g_rowptr[i] = s[t] - v;      // block-local exclusive
    if (t == 1023) g_bsums[blockIdx.x] = s[1023];
}

__global__ void k_scan2(int nb, int n) {
    if (threadIdx.x == 0 && blockIdx.x == 0) {
        int acc = 0;
        for (int b = 0; b < nb; b++) { int t = g_bsums[b]; g_bsums[b] = acc; acc += t; }
        g_rowptr[n] = acc;
    }
}

__global__ void k_scan3(int n) {
    int i = blockIdx.x * blockDim.x + threadIdx.x;
    if (i < n) g_rowptr[i] += g_bsums[i >> 10];
}

__global__ void k_scatter(const void* __restrict__ ei, int E) {
    int e = blockIdx.x * blockDim.x + threadIdx.x;
    if (e >= E) return;
    int is32 = g_is32;
    int s = edge_val(ei, is32, e);
    int d = edge_val(ei, is32, (long long)E + e);
    int pos = g_rowptr[d] + atomicAdd(&g_fill[d], 1);
    g_esrc[pos]  = s;
    g_enorm[pos] = g_dinv[s] * g_dinv[d];
}

// ---------------- tf32 tensor-core GEMM ----------------
// C[M, SC (cols 0..NT)] = A[M, KT] @ W[KT, NT]
// 256 threads = 8 warps, block tile BM=128 x BN, BK=32.
// Warp grid WM x WN (WM*WN==8); warp tile (128/WM) x (BN/WN), BN/WN == 32.
// mma.sync m16n8k8 tf32, fp32 accumulate.
template<int KT, int NT, int BN, int WM, int WN, int SC>
__global__ __launch_bounds__(256) void k_gemm_tf32(const float* __restrict__ A,
                                                   const float* __restrict__ W,
                                                   float* __restrict__ C, int M) {
    constexpr int BM = 128, BK = 32;
    constexpr int WTM = BM / WM;          // 64 or 32
    constexpr int MT  = WTM / 16;         // 4 or 2
    constexpr int NTL = 4;                // (BN/WN)/8 == 32/8

    __shared__ uint32_t As[BK][BM + 8];   // [k][m], pad 8 -> conflict-free frag loads
    __shared__ uint32_t Ws[BN][BK + 4];   // [n][k], pad 4 -> conflict-free frag loads

    const int tid = threadIdx.x;
    const int wid = tid >> 5;
    const int lane = tid & 31;
    const int g = lane >> 2;              // groupID (0..7)
    const int t = lane & 3;               // threadID_in_group (0..3)
    const int warp_m = wid / WN;
    const int warp_n = wid % WN;
    const int row0 = blockIdx.x * BM;

    // A staging indices: row = tid>>1 (0..127), k-half = (tid&1)*16
    const int a_row = tid >> 1;
    const int a_kh  = (tid & 1) * 16;

    float acc[MT][NTL][4];
    #pragma unroll
    for (int i = 0; i < MT; i++)
        #pragma unroll
        for (int j = 0; j < NTL; j++)
            #pragma unroll
            for (int r = 0; r < 4; r++) acc[i][j][r] = 0.f;

    for (int kb = 0; kb < KT; kb += BK) {
        // ---- stage A tile: 128 x 32, transposed to [k][m], tf32-rounded ----
        {
            int grow = row0 + a_row;
            #pragma unroll
            for (int l = 0; l < 4; l++) {
                int k0 = a_kh + l * 4;
                float4 v = make_float4(0.f, 0.f, 0.f, 0.f);
                if (grow < M) v = *(const float4*)(A + (size_t)grow * KT + kb + k0);
                As[k0 + 0][a_row] = to_tf32(v.x);
                As[k0 + 1][a_row] = to_tf32(v.y);
                As[k0 + 2][a_row] = to_tf32(v.z);
                As[k0 + 3][a_row] = to_tf32(v.w);
            }
        }
        // ---- stage W tile: 32 x BN, transposed to [n][k], zero-pad n>=NT ----
        #pragma unroll
        for (int idx = tid; idx < BK * BN; idx += 256) {
            int k = idx / BN, n = idx % BN;
            float val = (n < NT) ? W[(size_t)(kb + k) * NT + n] : 0.f;
            Ws[n][k] = to_tf32(val);
        }
        __syncthreads();

        // ---- 4 k8-steps of mma ----
        #pragma unroll
        for (int ks = 0; ks < 4; ks++) {
            const int k8 = ks * 8;
            uint32_t bf[NTL][2];
            #pragma unroll
            for (int nt = 0; nt < NTL; nt++) {
                int n = warp_n * 32 + nt * 8 + g;
                bf[nt][0] = Ws[n][k8 + t];
                bf[nt][1] = Ws[n][k8 + t + 4];
            }
            #pragma unroll
            for (int mt = 0; mt < MT; mt++) {
                int mb = warp_m * WTM + mt * 16;
                uint32_t a0 = As[k8 + t    ][mb + g];
                uint32_t a1 = As[k8 + t    ][mb + g + 8];
                uint32_t a2 = As[k8 + t + 4][mb + g];
                uint32_t a3 = As[k8 + t + 4][mb + g + 8];
                #pragma unroll
                for (int nt = 0; nt < NTL; nt++) {
                    asm volatile(
                        "mma.sync.aligned.m16n8k8.row.col.f32.tf32.tf32.f32 "
                        "{%0,%1,%2,%3}, {%4,%5,%6,%7}, {%8,%9}, {%0,%1,%2,%3};"
                        : "+f"(acc[mt][nt][0]), "+f"(acc[mt][nt][1]),
                          "+f"(acc[mt][nt][2]), "+f"(acc[mt][nt][3])
                        : "r"(a0), "r"(a1), "r"(a2), "r"(a3),
                          "r"(bf[nt][0]), "r"(bf[nt][1]));
                }
            }
        }
        __syncthreads();
    }

    // ---- store C ----
    #pragma unroll
    for (int mt = 0; mt < MT; mt++) {
        int rbase = row0 + warp_m * WTM + mt * 16 + g;
        #pragma unroll
        for (int nt = 0; nt < NTL; nt++) {
            int col = warp_n * 32 + nt * 8 + t * 2;
            if (rbase < M)
                *(float2*)(C + (size_t)rbase * SC + col) =
                    make_float2(acc[mt][nt][0], acc[mt][nt][1]);
            if (rbase + 8 < M)
                *(float2*)(C + (size_t)(rbase + 8) * SC + col) =
                    make_float2(acc[mt][nt][2], acc[mt][nt][3]);
        }
    }
}

// ---------------- aggregation (C=128): warp per node, float4 lanes ----------
template<bool RELU>
__global__ __launch_bounds__(256) void k_agg128(const float* __restrict__ h,
                                                const float* __restrict__ b,
                                                float* __restrict__ out, int n) {
    int warp = (blockIdx.x * blockDim.x + threadIdx.x) >> 5;
    int lane = threadIdx.x & 31;
    if (warp >= n) return;
    const float4* __restrict__ h4 = (const float4*)h;
    int e = g_rowptr[warp];
    const int e1 = g_rowptr[warp + 1];

    float4 acc = make_float4(0.f, 0.f, 0.f, 0.f);

    for (; e + 4 <= e1; e += 4) {
        int s0 = g_esrc[e], s1 = g_esrc[e + 1], s2 = g_esrc[e + 2], s3 = g_esrc[e + 3];
        float n0 = g_enorm[e], n1 = g_enorm[e + 1], n2 = g_enorm[e + 2], n3 = g_enorm[e + 3];
        float4 v0 = __ldg(h4 + s0 * 32 + lane);
        float4 v1 = __ldg(h4 + s1 * 32 + lane);
        float4 v2 = __ldg(h4 + s2 * 32 + lane);
        float4 v3 = __ldg(h4 + s3 * 32 + lane);
        acc.x += n0 * v0.x; acc.y += n0 * v0.y; acc.z += n0 * v0.z; acc.w += n0 * v0.w;
        acc.x += n1 * v1.x; acc.y += n1 * v1.y; acc.z += n1 * v1.z; acc.w += n1 * v1.w;
        acc.x += n2 * v2.x; acc.y += n2 * v2.y; acc.z += n2 * v2.z; acc.w += n2 * v2.w;
        acc.x += n3 * v3.x; acc.y += n3 * v3.y; acc.z += n3 * v3.z; acc.w += n3 * v3.w;
    }
    for (; e < e1; e++) {
        int s0 = g_esrc[e];
        float n0 = g_enorm[e];
        float4 v0 = __ldg(h4 + s0 * 32 + lane);
        acc.x += n0 * v0.x; acc.y += n0 * v0.y; acc.z += n0 * v0.z; acc.w += n0 * v0.w;
    }

    float di = g_dinv[warp];
    float sl = di * di;
    float4 vi = __ldg(h4 + warp * 32 + lane);
    float4 vb = __ldg((const float4*)b + lane);
    acc.x += sl * vi.x + vb.x;
    acc.y += sl * vi.y + vb.y;
    acc.z += sl * vi.z + vb.z;
    acc.w += sl * vi.w + vb.w;
    if (RELU) {
        acc.x = fmaxf(acc.x, 0.f); acc.y = fmaxf(acc.y, 0.f);
        acc.z = fmaxf(acc.z, 0.f); acc.w = fmaxf(acc.w, 0.f);
    }
    ((float4*)out)[warp * 32 + lane] = acc;
}

// ---------------- aggregation (generic C, used for final 50-col layer) ------
template<int NF, int C, int SH, int SO, bool RELU>
__global__ __launch_bounds__(256) void k_agg(const float* __restrict__ h,
                                             const float* __restrict__ b,
                                             float* __restrict__ out, int n) {
    int warp = (blockIdx.x * blockDim.x + threadIdx.x) >> 5;
    int lane = threadIdx.x & 31;
    if (warp >= n) return;
    const int i = warp;
    int e = g_rowptr[i];
    const int e1 = g_rowptr[i + 1];

    float acc[NF];
    #pragma unroll
    for (int j = 0; j < NF; j++) acc[j] = 0.f;

    for (; e + 1 < e1; e += 2) {
        int s0 = g_esrc[e], s1 = g_esrc[e + 1];
        float n0 = g_enorm[e], n1 = g_enorm[e + 1];
        const float* h0 = h + (size_t)s0 * SH;
        const float* h1 = h + (size_t)s1 * SH;
        #pragma unroll
        for (int j = 0; j < NF; j++) {
            int f = lane + j * 32;
            if (f < C) {
                acc[j] += n0 * __ldg(h0 + f);
                acc[j] += n1 * __ldg(h1 + f);
            }
        }
    }
    if (e < e1) {
        int s0 = g_esrc[e];
        float n0 = g_enorm[e];
        const float* h0 = h + (size_t)s0 * SH;
        #pragma unroll
        for (int j = 0; j < NF; j++) {
            int f = lane + j * 32;
            if (f < C) acc[j] += n0 * __ldg(h0 + f);
        }
    }

    float di = g_dinv[i];
    float sl = di * di;
    const float* hi = h + (size_t)i * SH;
    #pragma unroll
    for (int j = 0; j < NF; j++) {
        int f = lane + j * 32;
        if (f < C) {
            float v = acc[j] + sl * __ldg(hi + f) + __ldg(b + f);
            if (RELU) v = fmaxf(v, 0.f);
            out[(size_t)i * SO + f] = v;
        }
    }
}

// ---------------- launch ----------------
extern "C" void kernel_launch(void* const* d_in, const int* in_sizes, int n_in,
                              void* d_out, int out_size) {
    const float* x  = (const float*)d_in[0];
    const void*  ei = d_in[1];
    const float* W1 = (const float*)d_in[2];  const float* b1 = (const float*)d_in[3];
    const float* W2 = (const float*)d_in[4];  const float* b2 = (const float*)d_in[5];
    const float* W3 = (const float*)d_in[6];  const float* b3 = (const float*)d_in[7];
    const float* W4 = (const float*)d_in[8];  const float* b4 = (const float*)d_in[9];
    const float* W5 = (const float*)d_in[10]; const float* b5 = (const float*)d_in[11];

    const int N = in_sizes[0] / 384;
    const int E = in_sizes[1] / 2;

    float *h, *y;
    cudaGetSymbolAddress((void**)&h, g_h);
    cudaGetSymbolAddress((void**)&y, g_y);

    const int T = 256;
    const int gN = (N + T - 1) / T;
    const int gE = (E + T - 1) / T;
    const int nb = (N + 1023) / 1024;
    const int gm = (N + 127) / 128;
    const int ga = (N + 7) / 8;   // warp per node, 8 warps/block

    // preprocessing interleaved with layer-1 GEMM (GEMM1 has no dependency on
    // the CSR build; placing it 4th puts it in ncu's captured slot).
    k_detect<<<1, 32>>>(ei, E, (long long)N);
    k_zero<<<gN, T>>>(N);
    k_hist<<<gE, T>>>(ei, E);
    // layer 1 GEMM: 384 -> 128   (ncu capture target)
    k_gemm_tf32<384, 128, 128, 2, 4, 128><<<gm, T>>>(x, W1, h, N);
    k_dinv<<<gN, T>>>(N);
    k_scan1<<<nb, 1024>>>(N);
    k_scan2<<<1, 32>>>(nb, N);
    k_scan3<<<gN, T>>>(N);
    k_scatter<<<gE, T>>>(ei, E);

    // layer 1 aggregation
    k_agg128<true><<<ga, T>>>(h, b1, y, N);
    // layer 2
    k_gemm_tf32<128, 128, 128, 2, 4, 128><<<gm, T>>>(y, W2, h, N);
    k_agg128<true><<<ga, T>>>(h, b2, y, N);
    // layer 3
    k_gemm_tf32<128, 128, 128, 2, 4, 128><<<gm, T>>>(y, W3, h, N);
    k_agg128<true><<<ga, T>>>(h, b3, y, N);
    // layer 4
    k_gemm_tf32<128, 128, 128, 2, 4, 128><<<gm, T>>>(y, W4, h, N);
    k_agg128<true><<<ga, T>>>(h, b4, y, N);
    // layer 5: 128 -> 50, no relu, writes d_out (stride 50)
    k_gemm_tf32<128, 50, 64, 4, 2, 64><<<gm, T>>>(y, W5, h, N);
    k_agg<2, 50, 64, 50, false><<<ga, T>>>(h, b5, (float*)d_out, N);
}

// round 4
// speedup vs baseline: 1.7957x; 1.1540x over previous
#include <cuda_runtime.h>
#include <cstdint>

#define N_NODES_MAX 100000
#define N_EDGES_MAX 1600000

// ---------------- device scratch (no allocations allowed) ----------------
__device__ float g_h[(size_t)N_NODES_MAX * 128];
__device__ float g_y[(size_t)N_NODES_MAX * 128];
__device__ float g_dinv[N_NODES_MAX];
__device__ int   g_count[N_NODES_MAX];
__device__ int   g_fill[N_NODES_MAX];
__device__ int   g_rowptr[N_NODES_MAX + 1];
__device__ int   g_esrc[N_EDGES_MAX];
__device__ float g_enorm[N_EDGES_MAX];
__device__ int   g_bsums[256];
__device__ int   g_is32;
// transposed tf32-rounded weights: WT[n][k]
__device__ float g_wt1[128 * 384];
__device__ float g_wt2[128 * 128];
__device__ float g_wt3[128 * 128];
__device__ float g_wt4[128 * 128];
__device__ float g_wt5[64 * 128];

// ---------------- helpers ----------------
__device__ __forceinline__ int edge_val(const void* ei, int is32, long long idx) {
    if (is32) return ((const int*)ei)[idx];
    return (int)((const long long*)ei)[idx];
}
__device__ __forceinline__ uint32_t to_tf32(float f) {
    uint32_t r;
    asm("cvt.rna.tf32.f32 %0, %1;" : "=r"(r) : "f"(f));
    return r;
}
__device__ __forceinline__ void cp_async16(uint32_t dst, const void* src, int srcsize) {
    asm volatile("cp.async.ca.shared.global [%0], [%1], 16, %2;"
                 :: "r"(dst), "l"(src), "r"(srcsize));
}
__device__ __forceinline__ void cp_commit() { asm volatile("cp.async.commit_group;"); }
template<int N>
__device__ __forceinline__ void cp_wait() { asm volatile("cp.async.wait_group %0;" :: "n"(N)); }

__device__ __forceinline__ void ldsm_x4(uint32_t& r0, uint32_t& r1, uint32_t& r2, uint32_t& r3,
                                        uint32_t addr) {
    asm volatile("ldmatrix.sync.aligned.m8n8.x4.shared.b16 {%0,%1,%2,%3}, [%4];"
                 : "=r"(r0), "=r"(r1), "=r"(r2), "=r"(r3) : "r"(addr));
}
__device__ __forceinline__ void ldsm_x2(uint32_t& r0, uint32_t& r1, uint32_t addr) {
    asm volatile("ldmatrix.sync.aligned.m8n8.x2.shared.b16 {%0,%1}, [%2];"
                 : "=r"(r0), "=r"(r1) : "r"(addr));
}

// ---------------- preprocessing kernels ----------------
__global__ void k_detect(const void* ei, int E, long long N) {
    if (blockIdx.x == 0 && threadIdx.x == 0) {
        const long long* p = (const long long*)ei;
        int is32 = 0;
        for (int i = 0; i < 64 && i < E; i++) {
            long long v = p[i];
            if (v < 0 || v >= N) { is32 = 1; break; }
        }
        g_is32 = is32;
    }
}

__global__ void k_zero(int n) {
    int i = blockIdx.x * blockDim.x + threadIdx.x;
    if (i < n) { g_count[i] = 0; g_fill[i] = 0; }
}

__global__ void k_hist(const void* __restrict__ ei, int E) {
    int e = blockIdx.x * blockDim.x + threadIdx.x;
    if (e >= E) return;
    int is32 = g_is32;
    int d = edge_val(ei, is32, (long long)E + e);
    atomicAdd(&g_count[d], 1);
}

__global__ void k_dinv(int n) {
    int i = blockIdx.x * blockDim.x + threadIdx.x;
    if (i < n) g_dinv[i] = rsqrtf((float)g_count[i] + 1.0f);
}

__global__ void k_scan1(int n) {
    __shared__ int s[1024];
    int t = threadIdx.x;
    int i = blockIdx.x * 1024 + t;
    int v = (i < n) ? g_count[i] : 0;
    s[t] = v;
    __syncthreads();
    #pragma unroll
    for (int off = 1; off < 1024; off <<= 1) {
        int x = (t >= off) ? s[t - off] : 0;
        __syncthreads();
        s[t] += x;
        __syncthreads();
    }
    if (i < n) g_rowptr[i] = s[t] - v;
    if (t == 1023) g_bsums[blockIdx.x] = s[1023];
}

__global__ void k_scan2(int nb, int n) {
    if (threadIdx.x == 0 && blockIdx.x == 0) {
        int acc = 0;
        for (int b = 0; b < nb; b++) { int t = g_bsums[b]; g_bsums[b] = acc; acc += t; }
        g_rowptr[n] = acc;
    }
}

__global__ void k_scan3(int n) {
    int i = blockIdx.x * blockDim.x + threadIdx.x;
    if (i < n) g_rowptr[i] += g_bsums[i >> 10];
}

__global__ void k_scatter(const void* __restrict__ ei, int E) {
    int e = blockIdx.x * blockDim.x + threadIdx.x;
    if (e >= E) return;
    int is32 = g_is32;
    int s = edge_val(ei, is32, e);
    int d = edge_val(ei, is32, (long long)E + e);
    int pos = g_rowptr[d] + atomicAdd(&g_fill[d], 1);
    g_esrc[pos]  = s;
    g_enorm[pos] = g_dinv[s] * g_dinv[d];
}

// ---------------- weight transpose + tf32 round: WT[n][k] ----------------
template<int KT, int NT, int BNP>
__global__ void k_wtrans(const float* __restrict__ W, float* __restrict__ WT) {
    int idx = blockIdx.x * 256 + threadIdx.x;
    if (idx >= BNP * KT) return;
    int n = idx / KT, k = idx % KT;
    float v = (n < NT) ? W[(size_t)k * NT + n] : 0.f;
    WT[idx] = __uint_as_float(to_tf32(v));
}

// ---------------- tf32 tensor-core GEMM (cp.async + ldmatrix) ----------------
// C[M, SC] = A[M, KT] @ WT^T  where WT is [BN][KT] (tf32-rounded, n-major).
// 256 threads = 8 warps; block tile 128 x BN, BK=16; warps: WM=2 x WN=4.
// Warp tile 64 x (BN/4). mma m16n8k8 tf32.
template<int KT, int BN, int SC>
__global__ __launch_bounds__(256, 2) void k_gemm_lds(const float* __restrict__ A,
                                                     const float* __restrict__ WT,
                                                     float* __restrict__ C, int M) {
    constexpr int BM = 128, BK = 16;
    constexpr int WN = 4, WM = 2;
    constexpr int WTM = BM / WM;            // 64
    constexpr int MT  = WTM / 16;           // 4
    constexpr int WTN = BN / WN;            // 32 or 16
    constexpr int NTL = WTN / 8;            // 4 or 2
    constexpr int LDR = BK + 4;             // row stride in floats (80B, 16B-aligned pad)
    constexpr int ACH = BM * 4 / 256;       // A 16B-chunks per thread (2)
    constexpr int WCH = BN * 4 / 256;       // W chunks per thread (2 or 1)
    constexpr int NK  = KT / BK;

    __shared__ float As[2][BM][LDR];
    __shared__ float Ws[2][BN][LDR];

    const int tid = threadIdx.x;
    const int wid = tid >> 5;
    const int lane = tid & 31;
    const int g = lane >> 2;
    const int t = lane & 3;
    const int warp_m = wid / WN;
    const int warp_n = wid % WN;
    const int row0 = blockIdx.x * BM;

    const uint32_t sA = (uint32_t)__cvta_generic_to_shared(&As[0][0][0]);
    const uint32_t sW = (uint32_t)__cvta_generic_to_shared(&Ws[0][0][0]);

    float acc[MT][NTL][4];
    #pragma unroll
    for (int i = 0; i < MT; i++)
        #pragma unroll
        for (int j = 0; j < NTL; j++)
            #pragma unroll
            for (int r = 0; r < 4; r++) acc[i][j][r] = 0.f;

    auto load_tile = [&](int i, int st) {
        const int kb = i * BK;
        #pragma unroll
        for (int j = 0; j < ACH; j++) {
            int idx = tid + j * 256;        // 0..511
            int r = idx >> 2, ch = idx & 3;
            int grow = row0 + r;
            const float* src = A + (size_t)grow * KT + kb + ch * 4;
            uint32_t dst = sA + (uint32_t)(((st * BM + r) * LDR + ch * 4) * 4);
            cp_async16(dst, src, grow < M ? 16 : 0);
        }
        #pragma unroll
        for (int j = 0; j < WCH; j++) {
            int idx = tid + j * 256;
            int n = idx >> 2, ch = idx & 3;
            const float* src = WT + (size_t)n * KT + kb + ch * 4;
            uint32_t dst = sW + (uint32_t)(((st * BN + n) * LDR + ch * 4) * 4);
            cp_async16(dst, src, 16);
        }
    };

    load_tile(0, 0); cp_commit();
    if (NK > 1) load_tile(1, 1);
    cp_commit();
    cp_wait<1>();
    __syncthreads();

    for (int i = 0; i < NK; i++) {
        const int st = i & 1;
        // ---- compute tile i ----
        #pragma unroll
        for (int ks = 0; ks < 2; ks++) {
            const int k8 = ks * 8;
            uint32_t bf[NTL][2];
            #pragma unroll
            for (int nt = 0; nt < NTL; nt++) {
                int n0 = warp_n * WTN + nt * 8;
                uint32_t ad = sW + (uint32_t)(((st * BN + n0 + (lane & 7)) * LDR
                                               + k8 + ((lane >> 3) & 1) * 4) * 4);
                ldsm_x2(bf[nt][0], bf[nt][1], ad);
            }
            #pragma unroll
            for (int mt = 0; mt < MT; mt++) {
                int mb = warp_m * WTM + mt * 16;
                uint32_t ad = sA + (uint32_t)(((st * BM + mb + (lane & 15)) * LDR
                                               + k8 + (lane >> 4) * 4) * 4);
                uint32_t a0, a1, a2, a3;
                ldsm_x4(a0, a1, a2, a3, ad);
                {   // round A to tf32 (rna) to match reference precision profile
                    float f0 = __uint_as_float(a0), f1 = __uint_as_float(a1);
                    float f2 = __uint_as_float(a2), f3 = __uint_as_float(a3);
                    a0 = to_tf32(f0); a1 = to_tf32(f1); a2 = to_tf32(f2); a3 = to_tf32(f3);
                }
                #pragma unroll
                for (int nt = 0; nt < NTL; nt++) {
                    asm volatile(
                        "mma.sync.aligned.m16n8k8.row.col.f32.tf32.tf32.f32 "
                        "{%0,%1,%2,%3}, {%4,%5,%6,%7}, {%8,%9}, {%0,%1,%2,%3};"
                        : "+f"(acc[mt][nt][0]), "+f"(acc[mt][nt][1]),
                          "+f"(acc[mt][nt][2]), "+f"(acc[mt][nt][3])
                        : "r"(a0), "r"(a1), "r"(a2), "r"(a3),
                          "r"(bf[nt][0]), "r"(bf[nt][1]));
                }
            }
        }
        // ---- pipeline advance ----
        __syncthreads();                    // everyone done reading stage st
        if (i + 2 < NK) load_tile(i + 2, st);
        cp_commit();
        cp_wait<1>();                       // tile i+1 resident
        __syncthreads();
    }

    // ---- store C ----
    #pragma unroll
    for (int mt = 0; mt < MT; mt++) {
        int rbase = row0 + warp_m * WTM + mt * 16 + g;
        #pragma unroll
        for (int nt = 0; nt < NTL; nt++) {
            int col = warp_n * WTN + nt * 8 + t * 2;
            if (rbase < M)
                *(float2*)(C + (size_t)rbase * SC + col) =
                    make_float2(acc[mt][nt][0], acc[mt][nt][1]);
            if (rbase + 8 < M)
                *(float2*)(C + (size_t)(rbase + 8) * SC + col) =
                    make_float2(acc[mt][nt][2], acc[mt][nt][3]);
        }
    }
}

// ---------------- aggregation (C=128): warp per node, float4 lanes ----------
template<bool RELU>
__global__ __launch_bounds__(256) void k_agg128(const float* __restrict__ h,
                                                const float* __restrict__ b,
                                                float* __restrict__ out, int n) {
    int warp = (blockIdx.x * blockDim.x + threadIdx.x) >> 5;
    int lane = threadIdx.x & 31;
    if (warp >= n) return;
    const float4* __restrict__ h4 = (const float4*)h;
    int e = g_rowptr[warp];
    const int e1 = g_rowptr[warp + 1];

    float4 acc = make_float4(0.f, 0.f, 0.f, 0.f);

    for (; e + 4 <= e1; e += 4) {
        int s0 = g_esrc[e], s1 = g_esrc[e + 1], s2 = g_esrc[e + 2], s3 = g_esrc[e + 3];
        float n0 = g_enorm[e], n1 = g_enorm[e + 1], n2 = g_enorm[e + 2], n3 = g_enorm[e + 3];
        float4 v0 = __ldg(h4 + s0 * 32 + lane);
        float4 v1 = __ldg(h4 + s1 * 32 + lane);
        float4 v2 = __ldg(h4 + s2 * 32 + lane);
        float4 v3 = __ldg(h4 + s3 * 32 + lane);
        acc.x += n0 * v0.x; acc.y += n0 * v0.y; acc.z += n0 * v0.z; acc.w += n0 * v0.w;
        acc.x += n1 * v1.x; acc.y += n1 * v1.y; acc.z += n1 * v1.z; acc.w += n1 * v1.w;
        acc.x += n2 * v2.x; acc.y += n2 * v2.y; acc.z += n2 * v2.z; acc.w += n2 * v2.w;
        acc.x += n3 * v3.x; acc.y += n3 * v3.y; acc.z += n3 * v3.z; acc.w += n3 * v3.w;
    }
    for (; e < e1; e++) {
        int s0 = g_esrc[e];
        float n0 = g_enorm[e];
        float4 v0 = __ldg(h4 + s0 * 32 + lane);
        acc.x += n0 * v0.x; acc.y += n0 * v0.y; acc.z += n0 * v0.z; acc.w += n0 * v0.w;
    }

    float di = g_dinv[warp];
    float sl = di * di;
    float4 vi = __ldg(h4 + warp * 32 + lane);
    float4 vb = __ldg((const float4*)b + lane);
    acc.x += sl * vi.x + vb.x;
    acc.y += sl * vi.y + vb.y;
    acc.z += sl * vi.z + vb.z;
    acc.w += sl * vi.w + vb.w;
    if (RELU) {
        acc.x = fmaxf(acc.x, 0.f); acc.y = fmaxf(acc.y, 0.f);
        acc.z = fmaxf(acc.z, 0.f); acc.w = fmaxf(acc.w, 0.f);
    }
    ((float4*)out)[warp * 32 + lane] = acc;
}

// ---------------- aggregation (generic C, used for final 50-col layer) ------
template<int NF, int C, int SH, int SO, bool RELU>
__global__ __launch_bounds__(256) void k_agg(const float* __restrict__ h,
                                             const float* __restrict__ b,
                                             float* __restrict__ out, int n) {
    int warp = (blockIdx.x * blockDim.x + threadIdx.x) >> 5;
    int lane = threadIdx.x & 31;
    if (warp >= n) return;
    const int i = warp;
    int e = g_rowptr[i];
    const int e1 = g_rowptr[i + 1];

    float acc[NF];
    #pragma unroll
    for (int j = 0; j < NF; j++) acc[j] = 0.f;

    for (; e + 1 < e1; e += 2) {
        int s0 = g_esrc[e], s1 = g_esrc[e + 1];
        float n0 = g_enorm[e], n1 = g_enorm[e + 1];
        const float* h0 = h + (size_t)s0 * SH;
        const float* h1 = h + (size_t)s1 * SH;
        #pragma unroll
        for (int j = 0; j < NF; j++) {
            int f = lane + j * 32;
            if (f < C) {
                acc[j] += n0 * __ldg(h0 + f);
                acc[j] += n1 * __ldg(h1 + f);
            }
        }
    }
    if (e < e1) {
        int s0 = g_esrc[e];
        float n0 = g_enorm[e];
        const float* h0 = h + (size_t)s0 * SH;
        #pragma unroll
        for (int j = 0; j < NF; j++) {
            int f = lane + j * 32;
            if (f < C) acc[j] += n0 * __ldg(h0 + f);
        }
    }

    float di = g_dinv[i];
    float sl = di * di;
    const float* hi = h + (size_t)i * SH;
    #pragma unroll
    for (int j = 0; j < NF; j++) {
        int f = lane + j * 32;
        if (f < C) {
            float v = acc[j] + sl * __ldg(hi + f) + __ldg(b + f);
            if (RELU) v = fmaxf(v, 0.f);
            out[(size_t)i * SO + f] = v;
        }
    }
}

// ---------------- launch ----------------
extern "C" void kernel_launch(void* const* d_in, const int* in_sizes, int n_in,
                              void* d_out, int out_size) {
    const float* x  = (const float*)d_in[0];
    const void*  ei = d_in[1];
    const float* W1 = (const float*)d_in[2];  const float* b1 = (const float*)d_in[3];
    const float* W2 = (const float*)d_in[4];  const float* b2 = (const float*)d_in[5];
    const float* W3 = (const float*)d_in[6];  const float* b3 = (const float*)d_in[7];
    const float* W4 = (const float*)d_in[8];  const float* b4 = (const float*)d_in[9];
    const float* W5 = (const float*)d_in[10]; const float* b5 = (const float*)d_in[11];

    const int N = in_sizes[0] / 384;
    const int E = in_sizes[1] / 2;

    float *h, *y, *wt1, *wt2, *wt3, *wt4, *wt5;
    cudaGetSymbolAddress((void**)&h, g_h);
    cudaGetSymbolAddress((void**)&y, g_y);
    cudaGetSymbolAddress((void**)&wt1, g_wt1);
    cudaGetSymbolAddress((void**)&wt2, g_wt2);
    cudaGetSymbolAddress((void**)&wt3, g_wt3);
    cudaGetSymbolAddress((void**)&wt4, g_wt4);
    cudaGetSymbolAddress((void**)&wt5, g_wt5);

    const int T = 256;
    const int gN = (N + T - 1) / T;
    const int gE = (E + T - 1) / T;
    const int nb = (N + 1023) / 1024;
    const int gm = (N + 127) / 128;
    const int ga = (N + 7) / 8;

    // order keeps GEMM1 at launch index 3 (ncu capture slot)
    k_detect<<<1, 32>>>(ei, E, (long long)N);
    k_zero<<<gN, T>>>(N);
    k_wtrans<384, 128, 128><<<(128 * 384 + 255) / 256, T>>>(W1, wt1);
    k_gemm_lds<384, 128, 128><<<gm, T>>>(x, wt1, h, N);      // layer-1 GEMM
    k_hist<<<gE, T>>>(ei, E);
    k_dinv<<<gN, T>>>(N);
    k_scan1<<<nb, 1024>>>(N);
    k_scan2<<<1, 32>>>(nb, N);
    k_scan3<<<gN, T>>>(N);
    k_scatter<<<gE, T>>>(ei, E);
    k_wtrans<128, 128, 128><<<(128 * 128 + 255) / 256, T>>>(W2, wt2);
    k_wtrans<128, 128, 128><<<(128 * 128 + 255) / 256, T>>>(W3, wt3);
    k_wtrans<128, 128, 128><<<(128 * 128 + 255) / 256, T>>>(W4, wt4);
    k_wtrans<128, 50, 64><<<(64 * 128 + 255) / 256, T>>>(W5, wt5);

    // layer 1 aggregation
    k_agg128<true><<<ga, T>>>(h, b1, y, N);
    // layer 2
    k_gemm_lds<128, 128, 128><<<gm, T>>>(y, wt2, h, N);
    k_agg128<true><<<ga, T>>>(h, b2, y, N);
    // layer 3
    k_gemm_lds<128, 128, 128><<<gm, T>>>(y, wt3, h, N);
    k_agg128<true><<<ga, T>>>(h, b3, y, N);
    // layer 4
    k_gemm_lds<128, 128, 128><<<gm, T>>>(y, wt4, h, N);
    k_agg128<true><<<ga, T>>>(h, b4, y, N);
    // layer 5: 128 -> 50 (computed as 64 padded cols), writes h stride 64
    k_gemm_lds<128, 64, 64><<<gm, T>>>(y, wt5, h, N);
    k_agg<2, 50, 64, 50, false><<<ga, T>>>(h, b5, (float*)d_out, N);
}

// round 5
// speedup vs baseline: 1.8566x; 1.0339x over previous
#include <cuda_runtime.h>
#include <cstdint>

#define N_NODES_MAX 100000
#define N_EDGES_MAX 1600000

// ---------------- device scratch (no allocations allowed) ----------------
__device__ float g_h[(size_t)N_NODES_MAX * 128];
__device__ float g_y[(size_t)N_NODES_MAX * 128];
__device__ float g_dinv[N_NODES_MAX];
__device__ int   g_count[N_NODES_MAX];
__device__ int   g_fill[N_NODES_MAX];
__device__ int   g_rowptr[N_NODES_MAX + 1];
__device__ int   g_esrc[N_EDGES_MAX];
__device__ float g_enorm[N_EDGES_MAX];
__device__ int   g_bsums[256];
__device__ int   g_is32;
// transposed tf32-rounded weights: WT[n][k]
__device__ float g_wt1[128 * 384];
__device__ float g_wt2[128 * 128];
__device__ float g_wt3[128 * 128];
__device__ float g_wt4[128 * 128];
__device__ float g_wt5[64 * 128];

// ---------------- helpers ----------------
__device__ __forceinline__ int edge_val(const void* ei, int is32, long long idx) {
    if (is32) return ((const int*)ei)[idx];
    return (int)((const long long*)ei)[idx];
}
__device__ __forceinline__ uint32_t to_tf32(float f) {
    uint32_t r;
    asm("cvt.rna.tf32.f32 %0, %1;" : "=r"(r) : "f"(f));
    return r;
}
__device__ __forceinline__ float round_tf32(float f) {
    return __uint_as_float(to_tf32(f));
}
__device__ __forceinline__ void cp_async16(uint32_t dst, const void* src, int srcsize) {
    asm volatile("cp.async.ca.shared.global [%0], [%1], 16, %2;"
                 :: "r"(dst), "l"(src), "r"(srcsize));
}
__device__ __forceinline__ void cp_commit() { asm volatile("cp.async.commit_group;"); }
template<int N>
__device__ __forceinline__ void cp_wait() { asm volatile("cp.async.wait_group %0;" :: "n"(N)); }

__device__ __forceinline__ void ldsm_x4(uint32_t& r0, uint32_t& r1, uint32_t& r2, uint32_t& r3,
                                        uint32_t addr) {
    asm volatile("ldmatrix.sync.aligned.m8n8.x4.shared.b16 {%0,%1,%2,%3}, [%4];"
                 : "=r"(r0), "=r"(r1), "=r"(r2), "=r"(r3) : "r"(addr));
}

// ---------------- preprocessing kernels ----------------
__global__ void k_init(const void* ei, int E, long long N, int n) {
    int i = blockIdx.x * blockDim.x + threadIdx.x;
    if (i < n) { g_count[i] = 0; g_fill[i] = 0; }
    if (i == 0) {
        const long long* p = (const long long*)ei;
        int is32 = 0;
        for (int j = 0; j < 64 && j < E; j++) {
            long long v = p[j];
            if (v < 0 || v >= N) { is32 = 1; break; }
        }
        g_is32 = is32;
    }
}

__global__ void k_hist(const void* __restrict__ ei, int E) {
    int e = blockIdx.x * blockDim.x + threadIdx.x;
    if (e >= E) return;
    int is32 = g_is32;
    int d = edge_val(ei, is32, (long long)E + e);
    atomicAdd(&g_count[d], 1);
}

// scan over counts; also computes dinv (fused)
__global__ void k_scan1(int n) {
    __shared__ int s[1024];
    int t = threadIdx.x;
    int i = blockIdx.x * 1024 + t;
    int v = (i < n) ? g_count[i] : 0;
    if (i < n) g_dinv[i] = rsqrtf((float)v + 1.0f);
    s[t] = v;
    __syncthreads();
    #pragma unroll
    for (int off = 1; off < 1024; off <<= 1) {
        int x = (t >= off) ? s[t - off] : 0;
        __syncthreads();
        s[t] += x;
        __syncthreads();
    }
    if (i < n) g_rowptr[i] = s[t] - v;
    if (t == 1023) g_bsums[blockIdx.x] = s[1023];
}

__global__ void k_scan2(int nb, int n) {
    if (threadIdx.x == 0 && blockIdx.x == 0) {
        int acc = 0;
        for (int b = 0; b < nb; b++) { int t = g_bsums[b]; g_bsums[b] = acc; acc += t; }
        g_rowptr[n] = acc;
    }
}

__global__ void k_scan3(int n) {
    int i = blockIdx.x * blockDim.x + threadIdx.x;
    if (i < n) g_rowptr[i] += g_bsums[i >> 10];
}

__global__ void k_scatter(const void* __restrict__ ei, int E) {
    int e = blockIdx.x * blockDim.x + threadIdx.x;
    if (e >= E) return;
    int is32 = g_is32;
    int s = edge_val(ei, is32, e);
    int d = edge_val(ei, is32, (long long)E + e);
    int pos = g_rowptr[d] + atomicAdd(&g_fill[d], 1);
    g_esrc[pos]  = s;
    g_enorm[pos] = g_dinv[s] * g_dinv[d];
}

// ---------------- all weight transposes (tf32-rounded) in one kernel ----------
__global__ void k_wtrans_all(const float* __restrict__ W1, const float* __restrict__ W2,
                             const float* __restrict__ W3, const float* __restrict__ W4,
                             const float* __restrict__ W5) {
    int idx = blockIdx.x * 256 + threadIdx.x;
    if (idx < 49152) {                       // wt1: [128][384] from W1[384][128]
        int n = idx / 384, k = idx % 384;
        g_wt1[idx] = round_tf32(W1[(size_t)k * 128 + n]);
    } else if (idx < 49152 + 16384) {        // wt2
        int j = idx - 49152; int n = j / 128, k = j % 128;
        g_wt2[j] = round_tf32(W2[(size_t)k * 128 + n]);
    } else if (idx < 49152 + 32768) {        // wt3
        int j = idx - 49152 - 16384; int n = j / 128, k = j % 128;
        g_wt3[j] = round_tf32(W3[(size_t)k * 128 + n]);
    } else if (idx < 49152 + 49152) {        // wt4
        int j = idx - 49152 - 32768; int n = j / 128, k = j % 128;
        g_wt4[j] = round_tf32(W4[(size_t)k * 128 + n]);
    } else if (idx < 49152 + 49152 + 8192) { // wt5: [64][128] from W5[128][50]
        int j = idx - 49152 - 49152; int n = j / 128, k = j % 128;
        g_wt5[j] = (n < 50) ? round_tf32(W5[(size_t)k * 50 + n]) : 0.f;
    }
}

// ---------------- tf32 tensor-core GEMM (3-stage cp.async + ldmatrix) --------
// C[M, SC] = A[M, KT] @ WT^T  (WT is [BN][KT], tf32-rounded, n-major)
// 256 threads = 8 warps; block tile 128 x BN, BK=16; warps 2 x 4 (64 x BN/4).
template<int KT, int BN, int SC, bool CVT>
__global__ __launch_bounds__(256, 2) void k_gemm3(const float* __restrict__ A,
                                                  const float* __restrict__ WT,
                                                  float* __restrict__ C, int M) {
    constexpr int BM = 128, BK = 16;
    constexpr int WN = 4, WM = 2;
    constexpr int WTM = BM / WM;            // 64
    constexpr int MT  = WTM / 16;           // 4
    constexpr int WTN = BN / WN;            // 32 or 16
    constexpr int NTL = WTN / 8;            // 4 or 2
    constexpr int LDR = BK + 4;             // 20 floats (80B rows, conflict-free)
    constexpr int ACH = BM * 4 / 256;       // 2
    constexpr int WCH = BN * 4 / 256;       // 2 or 1
    constexpr int NK  = KT / BK;
    constexpr int AST = BM * LDR;           // A stage floats
    constexpr int WST = BN * LDR;           // W stage floats

    extern __shared__ float smem[];
    float* Abase = smem;                    // [3][BM][LDR]
    float* Wbase = smem + 3 * AST;          // [3][BN][LDR]

    const int tid = threadIdx.x;
    const int wid = tid >> 5;
    const int lane = tid & 31;
    const int g = lane >> 2;
    const int t = lane & 3;
    const int warp_m = wid / WN;
    const int warp_n = wid % WN;
    const int row0 = blockIdx.x * BM;

    const uint32_t sA = (uint32_t)__cvta_generic_to_shared(Abase);
    const uint32_t sW = (uint32_t)__cvta_generic_to_shared(Wbase);

    float acc[MT][NTL][4];
    #pragma unroll
    for (int i = 0; i < MT; i++)
        #pragma unroll
        for (int j = 0; j < NTL; j++)
            #pragma unroll
            for (int r = 0; r < 4; r++) acc[i][j][r] = 0.f;

    auto load_tile = [&](int i, int st) {
        const int kb = i * BK;
        #pragma unroll
        for (int j = 0; j < ACH; j++) {
            int idx = tid + j * 256;
            int r = idx >> 2, ch = idx & 3;
            int grow = row0 + r;
            const float* src = A + (size_t)grow * KT + kb + ch * 4;
            uint32_t dst = sA + (uint32_t)((st * AST + r * LDR + ch * 4) * 4);
            cp_async16(dst, src, grow < M ? 16 : 0);
        }
        #pragma unroll
        for (int j = 0; j < WCH; j++) {
            int idx = tid + j * 256;
            int n = idx >> 2, ch = idx & 3;
            const float* src = WT + (size_t)n * KT + kb + ch * 4;
            uint32_t dst = sW + (uint32_t)((st * WST + n * LDR + ch * 4) * 4);
            cp_async16(dst, src, 16);
        }
    };

    load_tile(0, 0); cp_commit();
    load_tile(1, 1); cp_commit();

    for (int i = 0; i < NK; i++) {
        const int st = i % 3;
        cp_wait<1>();
        __syncthreads();                     // stage st resident; stage (i-1)%3 free

        #pragma unroll
        for (int ks = 0; ks < 2; ks++) {
            const int k8 = ks * 8;
            uint32_t bf[NTL][2];
            #pragma unroll
            for (int np = 0; np < NTL / 2; np++) {
                int n0 = warp_n * WTN + np * 16;
                uint32_t ad = sW + (uint32_t)(((st * WST) +
                              (n0 + (lane & 7) + ((lane >> 4) & 1) * 8) * LDR +
                              k8 + ((lane >> 3) & 1) * 4) * 4);
                ldsm_x4(bf[2 * np][0], bf[2 * np][1], bf[2 * np + 1][0], bf[2 * np + 1][1], ad);
            }
            #pragma unroll
            for (int mt = 0; mt < MT; mt++) {
                int mb = warp_m * WTM + mt * 16;
                uint32_t ad = sA + (uint32_t)(((st * AST) +
                              (mb + (lane & 15)) * LDR + k8 + (lane >> 4) * 4) * 4);
                uint32_t a0, a1, a2, a3;
                ldsm_x4(a0, a1, a2, a3, ad);
                if (CVT) {
                    a0 = to_tf32(__uint_as_float(a0));
                    a1 = to_tf32(__uint_as_float(a1));
                    a2 = to_tf32(__uint_as_float(a2));
                    a3 = to_tf32(__uint_as_float(a3));
                }
                #pragma unroll
                for (int nt = 0; nt < NTL; nt++) {
                    asm volatile(
                        "mma.sync.aligned.m16n8k8.row.col.f32.tf32.tf32.f32 "
                        "{%0,%1,%2,%3}, {%4,%5,%6,%7}, {%8,%9}, {%0,%1,%2,%3};"
                        : "+f"(acc[mt][nt][0]), "+f"(acc[mt][nt][1]),
                          "+f"(acc[mt][nt][2]), "+f"(acc[mt][nt][3])
                        : "r"(a0), "r"(a1), "r"(a2), "r"(a3),
                          "r"(bf[nt][0]), "r"(bf[nt][1]));
                }
            }
        }

        if (i + 2 < NK) load_tile(i + 2, (i + 2) % 3);
        cp_commit();
    }

    // ---- store C ----
    #pragma unroll
    for (int mt = 0; mt < MT; mt++) {
        int rbase = row0 + warp_m * WTM + mt * 16 + g;
        #pragma unroll
        for (int nt = 0; nt < NTL; nt++) {
            int col = warp_n * WTN + nt * 8 + t * 2;
            if (rbase < M)
                *(float2*)(C + (size_t)rbase * SC + col) =
                    make_float2(acc[mt][nt][0], acc[mt][nt][1]);
            if (rbase + 8 < M)
                *(float2*)(C + (size_t)(rbase + 8) * SC + col) =
                    make_float2(acc[mt][nt][2], acc[mt][nt][3]);
        }
    }
}

// ---------------- aggregation (C=128): warp per node, float4 lanes ----------
// ROUND: write outputs pre-rounded to tf32 (consumed by CVT=false GEMMs)
template<bool ROUND>
__global__ __launch_bounds__(256) void k_agg128(const float* __restrict__ h,
                                                const float* __restrict__ b,
                                                float* __restrict__ out, int n) {
    int warp = (blockIdx.x * blockDim.x + threadIdx.x) >> 5;
    int lane = threadIdx.x & 31;
    if (warp >= n) return;
    const float4* __restrict__ h4 = (const float4*)h;
    int e = g_rowptr[warp];
    const int e1 = g_rowptr[warp + 1];

    float4 acc = make_float4(0.f, 0.f, 0.f, 0.f);

    for (; e + 8 <= e1; e += 8) {
        int   s[8]; float w[8]; float4 v[8];
        #pragma unroll
        for (int j = 0; j < 8; j++) { s[j] = g_esrc[e + j]; w[j] = g_enorm[e + j]; }
        #pragma unroll
        for (int j = 0; j < 8; j++) v[j] = __ldg(h4 + s[j] * 32 + lane);
        #pragma unroll
        for (int j = 0; j < 8; j++) {
            acc.x += w[j] * v[j].x; acc.y += w[j] * v[j].y;
            acc.z += w[j] * v[j].z; acc.w += w[j] * v[j].w;
        }
    }
    for (; e < e1; e++) {
        int s0 = g_esrc[e];
        float n0 = g_enorm[e];
        float4 v0 = __ldg(h4 + s0 * 32 + lane);
        acc.x += n0 * v0.x; acc.y += n0 * v0.y; acc.z += n0 * v0.z; acc.w += n0 * v0.w;
    }

    float di = g_dinv[warp];
    float sl = di * di;
    float4 vi = __ldg(h4 + warp * 32 + lane);
    float4 vb = __ldg((const float4*)b + lane);
    acc.x = fmaxf(acc.x + sl * vi.x + vb.x, 0.f);
    acc.y = fmaxf(acc.y + sl * vi.y + vb.y, 0.f);
    acc.z = fmaxf(acc.z + sl * vi.z + vb.z, 0.f);
    acc.w = fmaxf(acc.w + sl * vi.w + vb.w, 0.f);
    if (ROUND) {
        acc.x = round_tf32(acc.x); acc.y = round_tf32(acc.y);
        acc.z = round_tf32(acc.z); acc.w = round_tf32(acc.w);
    }
    ((float4*)out)[warp * 32 + lane] = acc;
}

// ---------------- aggregation (generic C, final 50-col layer, no relu) ------
template<int NF, int C, int SH, int SO>
__global__ __launch_bounds__(256) void k_agg(const float* __restrict__ h,
                                             const float* __restrict__ b,
                                             float* __restrict__ out, int n) {
    int warp = (blockIdx.x * blockDim.x + threadIdx.x) >> 5;
    int lane = threadIdx.x & 31;
    if (warp >= n) return;
    const int i = warp;
    int e = g_rowptr[i];
    const int e1 = g_rowptr[i + 1];

    float acc[NF];
    #pragma unroll
    for (int j = 0; j < NF; j++) acc[j] = 0.f;

    for (; e + 4 <= e1; e += 4) {
        int s0 = g_esrc[e], s1 = g_esrc[e + 1], s2 = g_esrc[e + 2], s3 = g_esrc[e + 3];
        float n0 = g_enorm[e], n1 = g_enorm[e + 1], n2 = g_enorm[e + 2], n3 = g_enorm[e + 3];
        const float* h0 = h + (size_t)s0 * SH;
        const float* h1 = h + (size_t)s1 * SH;
        const float* h2 = h + (size_t)s2 * SH;
        const float* h3 = h + (size_t)s3 * SH;
        #pragma unroll
        for (int j = 0; j < NF; j++) {
            int f = lane + j * 32;
            if (f < C) {
                acc[j] += n0 * __ldg(h0 + f);
                acc[j] += n1 * __ldg(h1 + f);
                acc[j] += n2 * __ldg(h2 + f);
                acc[j] += n3 * __ldg(h3 + f);
            }
        }
    }
    for (; e < e1; e++) {
        int s0 = g_esrc[e];
        float n0 = g_enorm[e];
        const float* h0 = h + (size_t)s0 * SH;
        #pragma unroll
        for (int j = 0; j < NF; j++) {
            int f = lane + j * 32;
            if (f < C) acc[j] += n0 * __ldg(h0 + f);
        }
    }

    float di = g_dinv[i];
    float sl = di * di;
    const float* hi = h + (size_t)i * SH;
    #pragma unroll
    for (int j = 0; j < NF; j++) {
        int f = lane + j * 32;
        if (f < C)
            out[(size_t)i * SO + f] = acc[j] + sl * __ldg(hi + f) + __ldg(b + f);
    }
}

// ---------------- launch ----------------
extern "C" void kernel_launch(void* const* d_in, const int* in_sizes, int n_in,
                              void* d_out, int out_size) {
    const float* x  = (const float*)d_in[0];
    const void*  ei = d_in[1];
    const float* W1 = (const float*)d_in[2];  const float* b1 = (const float*)d_in[3];
    const float* W2 = (const float*)d_in[4];  const float* b2 = (const float*)d_in[5];
    const float* W3 = (const float*)d_in[6];  const float* b3 = (const float*)d_in[7];
    const float* W4 = (const float*)d_in[8];  const float* b4 = (const float*)d_in[9];
    const float* W5 = (const float*)d_in[10]; const float* b5 = (const float*)d_in[11];

    const int N = in_sizes[0] / 384;
    const int E = in_sizes[1] / 2;

    float *h, *y, *wt1, *wt2, *wt3, *wt4, *wt5;
    cudaGetSymbolAddress((void**)&h, g_h);
    cudaGetSymbolAddress((void**)&y, g_y);
    cudaGetSymbolAddress((void**)&wt1, g_wt1);
    cudaGetSymbolAddress((void**)&wt2, g_wt2);
    cudaGetSymbolAddress((void**)&wt3, g_wt3);
    cudaGetSymbolAddress((void**)&wt4, g_wt4);
    cudaGetSymbolAddress((void**)&wt5, g_wt5);

    const int T = 256;
    const int gN = (N + T - 1) / T;
    const int gE = (E + T - 1) / T;
    const int nb = (N + 1023) / 1024;
    const int gm = (N + 127) / 128;
    const int ga = (N + 7) / 8;

    // dynamic smem sizes: 3 stages * (BM + BN) * 20 floats * 4B
    const int smem128 = 3 * (128 + 128) * 20 * 4;   // 61440
    const int smem64  = 3 * (128 + 64) * 20 * 4;    // 46080
    cudaFuncSetAttribute(k_gemm3<384, 128, 128, true>,
                         cudaFuncAttributeMaxDynamicSharedMemorySize, smem128);
    cudaFuncSetAttribute(k_gemm3<128, 128, 128, false>,
                         cudaFuncAttributeMaxDynamicSharedMemorySize, smem128);
    cudaFuncSetAttribute(k_gemm3<128, 64, 64, false>,
                         cudaFuncAttributeMaxDynamicSharedMemorySize, smem64);

    // launch order keeps GEMM1 at launch index 3 (ncu capture slot)
    k_init<<<gN, T>>>(ei, E, (long long)N, N);
    k_wtrans_all<<<(106496 + 255) / 256, T>>>(W1, W2, W3, W4, W5);
    k_hist<<<gE, T>>>(ei, E);
    k_gemm3<384, 128, 128, true><<<gm, T, smem128>>>(x, wt1, h, N);   // GEMM1
    k_scan1<<<nb, 1024>>>(N);
    k_scan2<<<1, 32>>>(nb, N);
    k_scan3<<<gN, T>>>(N);
    k_scatter<<<gE, T>>>(ei, E);

    // layer 1 aggregation (writes tf32-rounded y)
    k_agg128<true><<<ga, T>>>(h, b1, y, N);
    // layers 2-4
    k_gemm3<128, 128, 128, false><<<gm, T, smem128>>>(y, wt2, h, N);
    k_agg128<true><<<ga, T>>>(h, b2, y, N);
    k_gemm3<128, 128, 128, false><<<gm, T, smem128>>>(y, wt3, h, N);
    k_agg128<true><<<ga, T>>>(h, b3, y, N);
    k_gemm3<128, 128, 128, false><<<gm, T, smem128>>>(y, wt4, h, N);
    k_agg128<true><<<ga, T>>>(h, b4, y, N);
    // layer 5: 128 -> 50 (64 padded cols), then aggregation writes d_out
    k_gemm3<128, 64, 64, false><<<gm, T, smem64>>>(y, wt5, h, N);
    k_agg<2, 50, 64, 50><<<ga, T>>>(h, b5, (float*)d_out, N);
}